// round 6
// baseline (speedup 1.0000x reference)
#include <cuda_runtime.h>

namespace {
constexpr int K     = 9;
constexpr int NB    = 64;
constexpr int NH    = 32;
constexpr int NW    = 32;
constexpr int NCELL = NH * NW;       // 1024
constexpr int NT    = 50;
constexpr int NLAB  = 2 * K + 3;     // 21
constexpr int CH    = 2 * K + 2;     // 20
constexpr float THR = 80.0f;
constexpr float IMW = 640.0f;
constexpr float IMH = 480.0f;
constexpr float SIL = 0.6f;
constexpr float OBJ = 5.0f;
constexpr int   TPB  = 512;
constexpr int   NBLK = NB * NCELL / TPB;   // 128 blocks, 1 CTA/SM, single wave
constexpr float CELLW = IMW / NW;    // 20 px
constexpr float CELLH = IMH / NH;    // 15 px
}

__device__ float        g_partials[NBLK];
__device__ unsigned int g_count = 0;

__global__ __launch_bounds__(TPB) void region_loss_kernel(
    const float* __restrict__ out,
    const float* __restrict__ tgt,
    const int*   __restrict__ epoch_p,
    float*       __restrict__ loss)
{
    __shared__ float2 sXY[NT][K];                  // gt corners, pixel space
    __shared__ float sbx0[NT], sbx1[NT], sby0[NT], sby1[NT];
    __shared__ int   scell[NT];
    __shared__ unsigned s_inv[2];
    __shared__ float swarp[TPB / 32];
    __shared__ int   s_last;

    const int bid  = blockIdx.x;
    const int b    = bid >> 1;
    const int tid  = threadIdx.x;
    const int cell = ((bid & 1) << 9) | tid;       // 0..1023

    // ---- 1) prediction + epoch loads first (DRAM latency overlaps staging)
    const int epoch = epoch_p ? __ldg(epoch_p) : 20;
    const float* ob = out + (size_t)(b * CH) * NCELL + cell;
    float raw[2 * K + 1];
    #pragma unroll
    for (int c = 0; c < 2 * K + 1; c++) raw[c] = ob[c * NCELL];

    // ---- 2) stage targets (coalesced), pixel space
    const float* tb = tgt + (size_t)b * (NT * NLAB);
    for (int idx = tid; idx < NT * 2 * K; idx += TPB) {
        int t = idx / (2 * K), c = idx - t * (2 * K);
        float v = tb[t * NLAB + 1 + c];
        float* dst = (float*)&sXY[t][c >> 1];
        dst[c & 1] = v * ((c & 1) ? IMH : IMW);
    }
    if (tid < 64) {   // validity prefix via ballot (x0 != 0)
        bool v = (tid < NT) && (tb[tid * NLAB + 1] != 0.0f);
        unsigned m = __ballot_sync(0xffffffffu, v);
        if ((tid & 31) == 0) s_inv[tid >> 5] = ~m;
    }
    __syncthreads();

    // ---- 3) per-target bbox + cell index
    if (tid < NT) {
        float2 c0 = sXY[tid][0];
        float mnx = c0.x, mxx = c0.x, mny = c0.y, mxy = c0.y;
        #pragma unroll
        for (int k = 1; k < K; k++) {
            float2 c = sXY[tid][k];
            mnx = fminf(mnx, c.x); mxx = fmaxf(mxx, c.x);
            mny = fminf(mny, c.y); mxy = fmaxf(mxy, c.y);
        }
        sbx0[tid] = mnx; sbx1[tid] = mxx; sby0[tid] = mny; sby1[tid] = mxy;
        int gi0 = (int)floorf(c0.x * (1.0f / CELLW));
        int gj0 = (int)floorf(c0.y * (1.0f / CELLH));
        scell[tid] = (gi0 >= 0 && gi0 < NW && gj0 >= 0 && gj0 < NH)
                         ? gj0 * NW + gi0 : -1;
    }
    __syncthreads();

    const unsigned inv0 = s_inv[0], inv1 = s_inv[1];
    const int nv = inv0 ? (__ffs(inv0) - 1) : (inv1 ? 31 + __ffs(inv1) : 64);
    const bool do_conf = epoch > 15;
    const float i_f = (float)(cell & (NW - 1));
    const float j_f = (float)(cell >> 5);

    // ---- 4) predictions in pixel space
    raw[0]      = 1.0f / (1.0f + __expf(-raw[0]));
    raw[1]      = 1.0f / (1.0f + __expf(-raw[1]));
    float confp = 1.0f / (1.0f + __expf(-raw[2 * K]));

    float px[K], py[K];
    float pminx = 1e30f, pmaxx = -1e30f, pminy = 1e30f, pmaxy = -1e30f;
    #pragma unroll
    for (int k = 0; k < K; k++) {
        px[k] = (raw[2 * k]     + i_f) * CELLW;
        py[k] = (raw[2 * k + 1] + j_f) * CELLH;
        pminx = fminf(pminx, px[k]); pmaxx = fmaxf(pmaxx, px[k]);
        pminy = fminf(pminy, py[k]); pmaxy = fmaxf(pmaxy, py[k]);
    }

    const float inv_denK = (1.0f / (float)K) / (__expf(2.0f) - 1.0f + 1e-5f);

    // ---- 5) single branch-free target loop: hit select + silent boolean.
    // Exact gate: mean corner-conf > 0.6 requires >= 6 of 9 corners within THR
    // (each corner contributes < 1), and bbox overlap within THR.
    int  thit   = -1;
    bool silent = false;
    for (int t = 0; t < nv; t++) {
        thit = (scell[t] == cell) ? t : thit;           // select, no branch
        float sepx = fmaxf(sbx0[t] - pmaxx, pminx - sbx1[t]);
        float sepy = fmaxf(sby0[t] - pmaxy, pminy - sby1[t]);
        bool ovl = (sepx < THR) & (sepy < THR);
        int cnt = 0;
        #pragma unroll
        for (int k = 0; k < K; k++) {                   // branchless count
            float2 g = sXY[t][k];
            float dx = g.x - px[k], dy = g.y - py[k];
            float d2 = fmaf(dx, dx, dy * dy);
            cnt += (d2 < THR * THR);
        }
        bool need = ovl & (cnt >= 6);
        if (__any_sync(0xffffffffu, need)) {            // one uniform-ish branch
            float acc = 0.0f;
            #pragma unroll
            for (int k = 0; k < K; k++) {
                float2 g = sXY[t][k];
                float dx = g.x - px[k], dy = g.y - py[k];
                float d2 = fmaf(dx, dx, dy * dy);
                float c  = __expf(2.0f - sqrtf(d2) * (2.0f / THR)) - 1.0f;
                acc += (d2 < THR * THR) ? c : 0.0f;
            }
            silent |= need & (acc * inv_denK > SIL);
        }
    }

    // ---- 6) per-cell loss
    float lcl = 0.0f;
    if (thit >= 0) {
        float2 g0 = sXY[thit][0];
        float gx0 = floorf(g0.x * (1.0f / CELLW));
        float gy0 = floorf(g0.y * (1.0f / CELLH));
        float acc = 0.0f;
        #pragma unroll
        for (int k = 0; k < K; k++) {
            float2 g = sXY[thit][k];
            float ex = raw[2 * k]     - (g.x * (1.0f / CELLW) - gx0);
            float ey = raw[2 * k + 1] - (g.y * (1.0f / CELLH) - gy0);
            lcl += 0.5f * (ex * ex + ey * ey);
            float dx = g.x - px[k], dy = g.y - py[k];
            float d2 = fmaf(dx, dx, dy * dy);
            if (d2 < THR * THR)
                acc += __expf(2.0f - sqrtf(d2) * (2.0f / THR)) - 1.0f;
        }
        if (do_conf) {
            float e = confp - acc * inv_denK;
            lcl += 0.5f * OBJ * e * e;
        }
    } else if (do_conf) {
        lcl = silent ? 0.0f : 0.5f * confp * confp;     // NOOBJ, tconf = 0
    }

    // ---- 7) block reduce -> partial; last block reduces NBLK partials
    #pragma unroll
    for (int o = 16; o > 0; o >>= 1)
        lcl += __shfl_xor_sync(0xffffffffu, lcl, o);
    if ((tid & 31) == 0) swarp[tid >> 5] = lcl;
    __syncthreads();
    if (tid < TPB / 32) {              // 16 lanes
        float v = swarp[tid];
        #pragma unroll
        for (int o = 8; o > 0; o >>= 1)
            v += __shfl_xor_sync(0xffffu, v, o);
        if (tid == 0) {
            g_partials[bid] = v;
            __threadfence();
            unsigned old = atomicAdd(&g_count, 1);
            s_last = (old == NBLK - 1) ? 1 : 0;
        }
    }
    __syncthreads();
    if (s_last) {
        if (tid < NBLK) {              // 128 lanes -> 4 warp sums
            float v = g_partials[tid];
            #pragma unroll
            for (int o = 16; o > 0; o >>= 1)
                v += __shfl_xor_sync(0xffffffffu, v, o);
            if ((tid & 31) == 0) swarp[tid >> 5] = v;
        }
        __syncthreads();
        if (tid == 0) {
            loss[0] = swarp[0] + swarp[1] + swarp[2] + swarp[3];
            g_count = 0;   // reset for next graph replay
        }
    }
}

extern "C" void kernel_launch(void* const* d_in, const int* in_sizes, int n_in,
                              void* d_out, int out_size)
{
    const float* output = (const float*)d_in[0];
    const float* target = (const float*)d_in[1];
    const int*   epoch  = (n_in > 2) ? (const int*)d_in[2] : nullptr;
    float* loss = (float*)d_out;

    region_loss_kernel<<<NBLK, TPB>>>(output, target, epoch, loss);
    (void)in_sizes; (void)out_size;
}

// round 7
// speedup vs baseline: 1.0194x; 1.0194x over previous
#include <cuda_runtime.h>

namespace {
constexpr int K     = 9;
constexpr int NB    = 64;
constexpr int NH    = 32;
constexpr int NW    = 32;
constexpr int NCELL = NH * NW;       // 1024
constexpr int NT    = 50;
constexpr int NLAB  = 2 * K + 3;     // 21
constexpr int CH    = 2 * K + 2;     // 20
constexpr float THR = 80.0f;
constexpr float IMW = 640.0f;
constexpr float IMH = 480.0f;
constexpr float SIL = 0.6f;
constexpr float OBJ = 5.0f;
constexpr int   TPB  = 512;
constexpr int   NBLK = NB * NCELL / TPB;   // 128 blocks, 1 CTA/SM, single wave
constexpr float CELLW = IMW / NW;    // 20 px
constexpr float CELLH = IMH / NH;    // 15 px
}

__device__ float        g_partials[NBLK];
__device__ unsigned int g_count = 0;

__global__ __launch_bounds__(TPB) void region_loss_kernel(
    const float* __restrict__ out,
    const float* __restrict__ tgt,
    const int*   __restrict__ epoch_p,
    float*       __restrict__ loss)
{
    __shared__ float2 sXY[NT][K];                  // gt corners, pixel space
    __shared__ float sbx0[NT], sbx1[NT], sby0[NT], sby1[NT];
    __shared__ int   scell[NT];
    __shared__ unsigned s_inv[2];
    __shared__ float swarp[TPB / 32];
    __shared__ int   s_last;

    const int bid  = blockIdx.x;
    const int b    = bid >> 1;
    const int tid  = threadIdx.x;
    const int cell = ((bid & 1) << 9) | tid;       // 0..1023

    // ---- 1) prediction + epoch loads first (DRAM latency overlaps staging)
    const int epoch = epoch_p ? __ldg(epoch_p) : 20;
    const float* ob = out + (size_t)(b * CH) * NCELL + cell;
    float raw[2 * K + 1];
    #pragma unroll
    for (int c = 0; c < 2 * K + 1; c++) raw[c] = ob[c * NCELL];

    // ---- 2) stage targets (coalesced), pixel space
    const float* tb = tgt + (size_t)b * (NT * NLAB);
    for (int idx = tid; idx < NT * 2 * K; idx += TPB) {
        int t = idx / (2 * K), c = idx - t * (2 * K);
        float v = tb[t * NLAB + 1 + c];
        float* dst = (float*)&sXY[t][c >> 1];
        dst[c & 1] = v * ((c & 1) ? IMH : IMW);
    }
    if (tid < 64) {   // validity prefix via ballot (x0 != 0)
        bool v = (tid < NT) && (tb[tid * NLAB + 1] != 0.0f);
        unsigned m = __ballot_sync(0xffffffffu, v);
        if ((tid & 31) == 0) s_inv[tid >> 5] = ~m;
    }
    __syncthreads();

    // ---- 3) per-target bbox + cell index
    if (tid < NT) {
        float2 c0 = sXY[tid][0];
        float mnx = c0.x, mxx = c0.x, mny = c0.y, mxy = c0.y;
        #pragma unroll
        for (int k = 1; k < K; k++) {
            float2 c = sXY[tid][k];
            mnx = fminf(mnx, c.x); mxx = fmaxf(mxx, c.x);
            mny = fminf(mny, c.y); mxy = fmaxf(mxy, c.y);
        }
        sbx0[tid] = mnx; sbx1[tid] = mxx; sby0[tid] = mny; sby1[tid] = mxy;
        int gi0 = (int)floorf(c0.x * (1.0f / CELLW));
        int gj0 = (int)floorf(c0.y * (1.0f / CELLH));
        scell[tid] = (gi0 >= 0 && gi0 < NW && gj0 >= 0 && gj0 < NH)
                         ? gj0 * NW + gi0 : -1;
    }
    __syncthreads();

    const unsigned inv0 = s_inv[0], inv1 = s_inv[1];
    const int nv = inv0 ? (__ffs(inv0) - 1) : (inv1 ? 31 + __ffs(inv1) : 64);
    const bool do_conf = epoch > 15;
    const float i_f = (float)(cell & (NW - 1));
    const float j_f = (float)(cell >> 5);

    // ---- 4) predictions in pixel space
    raw[0]      = 1.0f / (1.0f + __expf(-raw[0]));
    raw[1]      = 1.0f / (1.0f + __expf(-raw[1]));
    float confp = 1.0f / (1.0f + __expf(-raw[2 * K]));

    float px[K], py[K];
    float pminx = 1e30f, pmaxx = -1e30f, pminy = 1e30f, pmaxy = -1e30f;
    #pragma unroll
    for (int k = 0; k < K; k++) {
        px[k] = (raw[2 * k]     + i_f) * CELLW;
        py[k] = (raw[2 * k + 1] + j_f) * CELLH;
        pminx = fminf(pminx, px[k]); pmaxx = fmaxf(pmaxx, px[k]);
        pminy = fminf(pminy, py[k]); pmaxy = fmaxf(pmaxy, py[k]);
    }

    // warp-wide pred bbox (for uniform per-target pruning)
    float wminx = pminx, wmaxx = pmaxx, wminy = pminy, wmaxy = pmaxy;
    #pragma unroll
    for (int o = 16; o > 0; o >>= 1) {
        wminx = fminf(wminx, __shfl_xor_sync(0xffffffffu, wminx, o));
        wmaxx = fmaxf(wmaxx, __shfl_xor_sync(0xffffffffu, wmaxx, o));
        wminy = fminf(wminy, __shfl_xor_sync(0xffffffffu, wminy, o));
        wmaxy = fmaxf(wmaxy, __shfl_xor_sync(0xffffffffu, wmaxy, o));
    }

    const float inv_denK = (1.0f / (float)K) / (__expf(2.0f) - 1.0f + 1e-5f);

    // ---- 5) target loop with warp-uniform skip.
    // Warp-bbox separation >= THR  =>  every lane, every corner dist >= THR
    //   => contribution exactly 0 (silent unaffected). Hit select always runs.
    int  thit   = -1;
    bool silent = false;
    for (int t = 0; t < nv; t++) {
        thit = (scell[t] == cell) ? t : thit;           // select, no branch
        float wsepx = fmaxf(sbx0[t] - wmaxx, wminx - sbx1[t]);
        float wsepy = fmaxf(sby0[t] - wmaxy, wminy - sby1[t]);
        if (wsepx >= THR || wsepy >= THR) continue;     // warp-uniform skip
        int cnt = 0;
        #pragma unroll
        for (int k = 0; k < K; k++) {                   // branchless count
            float2 g = sXY[t][k];
            float dx = g.x - px[k], dy = g.y - py[k];
            float d2 = fmaf(dx, dx, dy * dy);
            cnt += (d2 < THR * THR);
        }
        // mean > 0.6 needs >= 6 of 9 corners within THR (each term < 1)
        bool need = (cnt >= 6);
        if (__any_sync(0xffffffffu, need)) {
            float acc = 0.0f;
            #pragma unroll
            for (int k = 0; k < K; k++) {
                float2 g = sXY[t][k];
                float dx = g.x - px[k], dy = g.y - py[k];
                float d2 = fmaf(dx, dx, dy * dy);
                float c  = __expf(2.0f - sqrtf(d2) * (2.0f / THR)) - 1.0f;
                acc += (d2 < THR * THR) ? c : 0.0f;
            }
            silent |= need & (acc * inv_denK > SIL);
        }
    }

    // ---- 6) per-cell loss
    float lcl = 0.0f;
    if (thit >= 0) {
        float2 g0 = sXY[thit][0];
        float gx0 = floorf(g0.x * (1.0f / CELLW));
        float gy0 = floorf(g0.y * (1.0f / CELLH));
        float acc = 0.0f;
        #pragma unroll
        for (int k = 0; k < K; k++) {
            float2 g = sXY[thit][k];
            float ex = raw[2 * k]     - (g.x * (1.0f / CELLW) - gx0);
            float ey = raw[2 * k + 1] - (g.y * (1.0f / CELLH) - gy0);
            lcl += 0.5f * (ex * ex + ey * ey);
            float dx = g.x - px[k], dy = g.y - py[k];
            float d2 = fmaf(dx, dx, dy * dy);
            if (d2 < THR * THR)
                acc += __expf(2.0f - sqrtf(d2) * (2.0f / THR)) - 1.0f;
        }
        if (do_conf) {
            float e = confp - acc * inv_denK;
            lcl += 0.5f * OBJ * e * e;
        }
    } else if (do_conf) {
        lcl = silent ? 0.0f : 0.5f * confp * confp;     // NOOBJ, tconf = 0
    }

    // ---- 7) block reduce -> partial; last block reduces NBLK partials
    #pragma unroll
    for (int o = 16; o > 0; o >>= 1)
        lcl += __shfl_xor_sync(0xffffffffu, lcl, o);
    if ((tid & 31) == 0) swarp[tid >> 5] = lcl;
    __syncthreads();
    if (tid < TPB / 32) {              // 16 lanes
        float v = swarp[tid];
        #pragma unroll
        for (int o = 8; o > 0; o >>= 1)
            v += __shfl_xor_sync(0xffffu, v, o);
        if (tid == 0) {
            g_partials[bid] = v;
            __threadfence();
            unsigned old = atomicAdd(&g_count, 1);
            s_last = (old == NBLK - 1) ? 1 : 0;
        }
    }
    __syncthreads();
    if (s_last) {
        if (tid < NBLK) {              // 128 lanes -> 4 warp sums
            float v = g_partials[tid];
            #pragma unroll
            for (int o = 16; o > 0; o >>= 1)
                v += __shfl_xor_sync(0xffffffffu, v, o);
            if ((tid & 31) == 0) swarp[tid >> 5] = v;
        }
        __syncthreads();
        if (tid == 0) {
            loss[0] = swarp[0] + swarp[1] + swarp[2] + swarp[3];
            g_count = 0;   // reset for next graph replay
        }
    }
}

extern "C" void kernel_launch(void* const* d_in, const int* in_sizes, int n_in,
                              void* d_out, int out_size)
{
    const float* output = (const float*)d_in[0];
    const float* target = (const float*)d_in[1];
    const int*   epoch  = (n_in > 2) ? (const int*)d_in[2] : nullptr;
    float* loss = (float*)d_out;

    region_loss_kernel<<<NBLK, TPB>>>(output, target, epoch, loss);
    (void)in_sizes; (void)out_size;
}

// round 8
// speedup vs baseline: 1.0283x; 1.0087x over previous
#include <cuda_runtime.h>

namespace {
constexpr int K     = 9;
constexpr int NB    = 64;
constexpr int NH    = 32;
constexpr int NW    = 32;
constexpr int NCELL = NH * NW;       // 1024
constexpr int NT    = 50;
constexpr int NLAB  = 2 * K + 3;     // 21
constexpr int CH    = 2 * K + 2;     // 20
constexpr float THR = 80.0f;
constexpr float IMW = 640.0f;
constexpr float IMH = 480.0f;
constexpr float SIL = 0.6f;
constexpr float OBJ = 5.0f;
constexpr int   TPB  = 512;
constexpr int   NBLK = NB * NCELL / TPB;   // 128 blocks, 1 CTA/SM, single wave
constexpr float CELLW = IMW / NW;    // 20 px
constexpr float CELLH = IMH / NH;    // 15 px
constexpr unsigned FULL = 0xffffffffu;
}

__device__ float        g_partials[NBLK];
__device__ unsigned int g_count = 0;

__global__ __launch_bounds__(TPB) void region_loss_kernel(
    const float* __restrict__ out,
    const float* __restrict__ tgt,
    const int*   __restrict__ epoch_p,
    float*       __restrict__ loss)
{
    __shared__ float2 sXY[NT][K];                  // gt corners, pixel space
    __shared__ float swarp[TPB / 32];
    __shared__ int   s_last;

    const int bid  = blockIdx.x;
    const int b    = bid >> 1;
    const int tid  = threadIdx.x;
    const int lane = tid & 31;
    const int cell = ((bid & 1) << 9) | tid;       // 0..1023; warp = one row span
    const int wbase = cell & ~31;                  // warp's first cell (uniform)

    // ---- 1) prediction + epoch loads first (DRAM latency overlaps staging)
    const int epoch = epoch_p ? __ldg(epoch_p) : 20;
    const float* ob = out + (size_t)(b * CH) * NCELL + cell;
    float raw[2 * K + 1];
    #pragma unroll
    for (int c = 0; c < 2 * K + 1; c++) raw[c] = ob[c * NCELL];

    // ---- 2) stage targets (coalesced), pixel space — the ONLY barrier deps
    const float* tb = tgt + (size_t)b * (NT * NLAB);
    for (int idx = tid; idx < NT * 2 * K; idx += TPB) {
        int t = idx / (2 * K), c = idx - t * (2 * K);
        float v = tb[t * NLAB + 1 + c];
        float* dst = (float*)&sXY[t][c >> 1];
        dst[c & 1] = v * ((c & 1) ? IMH : IMW);
    }
    __syncthreads();

    // ---- 3) lane-parallel target metadata (lane t owns target t), registers only
    float tbx0, tbx1, tby0, tby1;
    int   cellv;
    {
        float2 c0 = sXY[lane][0];
        float mnx = c0.x, mxx = c0.x, mny = c0.y, mxy = c0.y;
        #pragma unroll
        for (int k = 1; k < K; k++) {
            float2 c = sXY[lane][k];
            mnx = fminf(mnx, c.x); mxx = fmaxf(mxx, c.x);
            mny = fminf(mny, c.y); mxy = fmaxf(mxy, c.y);
        }
        tbx0 = mnx; tbx1 = mxx; tby0 = mny; tby1 = mxy;
        int gi0 = (int)floorf(c0.x * (1.0f / CELLW));
        int gj0 = (int)floorf(c0.y * (1.0f / CELLH));
        cellv = (gi0 >= 0 && gi0 < NW && gj0 >= 0 && gj0 < NH)
                    ? gj0 * NW + gi0 : -1;
        // validity prefix (x0 != 0 survives the IMW scaling) via 2 ballots
        unsigned inv0 = ~__ballot_sync(FULL, c0.x != 0.0f);
        bool v2 = (lane + 32 < NT) && (sXY[lane + 32][0].x != 0.0f);
        unsigned inv1 = ~__ballot_sync(FULL, v2);   // bits >=18 always set
        int nv_ = inv0 ? (__ffs(inv0) - 1) : (31 + __ffs(inv1));
        cellv = (lane < nv_) ? cellv : -1;          // fold validity into cell
        // stash nv in a register shared by all lanes (uniform)
        tbx0 = (lane < nv_) ? tbx0 : 1e30f;         // invalid -> never overlaps
        tbx1 = (lane < nv_) ? tbx1 : -1e30f;
        // keep nv for the rare nv>32 path
        #define NV nv_
        // ---- 4) predictions in pixel space
        const bool do_conf = epoch > 15;
        const float i_f = (float)(cell & (NW - 1));
        const float j_f = (float)(cell >> 5);

        raw[0]      = 1.0f / (1.0f + __expf(-raw[0]));
        raw[1]      = 1.0f / (1.0f + __expf(-raw[1]));
        float confp = 1.0f / (1.0f + __expf(-raw[2 * K]));

        float px[K], py[K];
        float pminx = 1e30f, pmaxx = -1e30f, pminy = 1e30f, pmaxy = -1e30f;
        #pragma unroll
        for (int k = 0; k < K; k++) {
            px[k] = (raw[2 * k]     + i_f) * CELLW;
            py[k] = (raw[2 * k + 1] + j_f) * CELLH;
            pminx = fminf(pminx, px[k]); pmaxx = fmaxf(pmaxx, px[k]);
            pminy = fminf(pminy, py[k]); pmaxy = fmaxf(pmaxy, py[k]);
        }

        // warp-wide pred bbox
        float wminx = pminx, wmaxx = pmaxx, wminy = pminy, wmaxy = pmaxy;
        #pragma unroll
        for (int o = 16; o > 0; o >>= 1) {
            wminx = fminf(wminx, __shfl_xor_sync(FULL, wminx, o));
            wmaxx = fmaxf(wmaxx, __shfl_xor_sync(FULL, wmaxx, o));
            wminy = fminf(wminy, __shfl_xor_sync(FULL, wminy, o));
            wmaxy = fmaxf(wmaxy, __shfl_xor_sync(FULL, wmaxy, o));
        }

        // ---- 5) one-shot survivor + hit masks (lane t evaluates target t)
        bool ovl = !(fmaxf(tbx0 - wmaxx, wminx - tbx1) >= THR ||
                     fmaxf(tby0 - wmaxy, wminy - tby1) >= THR);
        unsigned survm = __ballot_sync(FULL, ovl);
        bool inw = (cellv >= wbase) && (cellv < wbase + 32);
        unsigned hitm = __ballot_sync(FULL, inw);

        int thit = -1;
        for (unsigned hm = hitm; hm; hm &= hm - 1) {   // ascending t: last wins
            int t  = __ffs(hm) - 1;
            int sc = __shfl_sync(FULL, cellv, t);
            thit = (sc == cell) ? t : thit;
        }

        const float inv_denK = (1.0f / (float)K) / (__expf(2.0f) - 1.0f + 1e-5f);

        // ---- 6) survivor-only conf loop (exact: skipped targets contribute 0)
        bool silent = false;
        for (unsigned m = survm; m; m &= m - 1) {
            int t = __ffs(m) - 1;
            int cnt = 0;
            #pragma unroll
            for (int k = 0; k < K; k++) {
                float2 g = sXY[t][k];
                float dx = g.x - px[k], dy = g.y - py[k];
                float d2 = fmaf(dx, dx, dy * dy);
                cnt += (d2 < THR * THR);
            }
            // mean > 0.6 needs >= 6 of 9 corners within THR (each term < 1)
            bool need = (cnt >= 6);
            if (__any_sync(FULL, need)) {
                float acc = 0.0f;
                #pragma unroll
                for (int k = 0; k < K; k++) {
                    float2 g = sXY[t][k];
                    float dx = g.x - px[k], dy = g.y - py[k];
                    float d2 = fmaf(dx, dx, dy * dy);
                    float cc = __expf(2.0f - sqrtf(d2) * (2.0f / THR)) - 1.0f;
                    acc += (d2 < THR * THR) ? cc : 0.0f;
                }
                silent |= need & (acc * inv_denK > SIL);
            }
        }

        // ---- 6b) rare general path for targets t in [32, nv)
        if (NV > 32) {
            int t2 = lane + 32;
            float bx0 = 1e30f, bx1 = -1e30f, by0 = 1e30f, by1 = -1e30f;
            int cv2 = -1;
            if (t2 < NV) {
                float2 c2 = sXY[t2][0];
                bx0 = c2.x; bx1 = c2.x; by0 = c2.y; by1 = c2.y;
                #pragma unroll
                for (int k = 1; k < K; k++) {
                    float2 c = sXY[t2][k];
                    bx0 = fminf(bx0, c.x); bx1 = fmaxf(bx1, c.x);
                    by0 = fminf(by0, c.y); by1 = fmaxf(by1, c.y);
                }
                int gi0 = (int)floorf(c2.x * (1.0f / CELLW));
                int gj0 = (int)floorf(c2.y * (1.0f / CELLH));
                cv2 = (gi0 >= 0 && gi0 < NW && gj0 >= 0 && gj0 < NH)
                          ? gj0 * NW + gi0 : -1;
            }
            bool ovl2 = !(fmaxf(bx0 - wmaxx, wminx - bx1) >= THR ||
                          fmaxf(by0 - wmaxy, wminy - by1) >= THR);
            unsigned survm2 = __ballot_sync(FULL, ovl2);
            bool inw2 = (cv2 >= wbase) && (cv2 < wbase + 32);
            for (unsigned hm = __ballot_sync(FULL, inw2); hm; hm &= hm - 1) {
                int t = __ffs(hm) - 1;
                int sc = __shfl_sync(FULL, cv2, t);
                thit = (sc == cell) ? (t + 32) : thit;
            }
            for (unsigned m = survm2; m; m &= m - 1) {
                int t = (__ffs(m) - 1) + 32;
                int cnt = 0;
                #pragma unroll
                for (int k = 0; k < K; k++) {
                    float2 g = sXY[t][k];
                    float dx = g.x - px[k], dy = g.y - py[k];
                    float d2 = fmaf(dx, dx, dy * dy);
                    cnt += (d2 < THR * THR);
                }
                bool need = (cnt >= 6);
                if (__any_sync(FULL, need)) {
                    float acc = 0.0f;
                    #pragma unroll
                    for (int k = 0; k < K; k++) {
                        float2 g = sXY[t][k];
                        float dx = g.x - px[k], dy = g.y - py[k];
                        float d2 = fmaf(dx, dx, dy * dy);
                        float cc = __expf(2.0f - sqrtf(d2) * (2.0f / THR)) - 1.0f;
                        acc += (d2 < THR * THR) ? cc : 0.0f;
                    }
                    silent |= need & (acc * inv_denK > SIL);
                }
            }
        }
        #undef NV

        // ---- 7) per-cell loss
        float lcl = 0.0f;
        if (thit >= 0) {
            float2 g0 = sXY[thit][0];
            float gx0 = floorf(g0.x * (1.0f / CELLW));
            float gy0 = floorf(g0.y * (1.0f / CELLH));
            float acc = 0.0f;
            #pragma unroll
            for (int k = 0; k < K; k++) {
                float2 g = sXY[thit][k];
                float ex = raw[2 * k]     - (g.x * (1.0f / CELLW) - gx0);
                float ey = raw[2 * k + 1] - (g.y * (1.0f / CELLH) - gy0);
                lcl += 0.5f * (ex * ex + ey * ey);
                float dx = g.x - px[k], dy = g.y - py[k];
                float d2 = fmaf(dx, dx, dy * dy);
                if (d2 < THR * THR)
                    acc += __expf(2.0f - sqrtf(d2) * (2.0f / THR)) - 1.0f;
            }
            if (do_conf) {
                float e = confp - acc * inv_denK;
                lcl += 0.5f * OBJ * e * e;
            }
        } else if (do_conf) {
            lcl = silent ? 0.0f : 0.5f * confp * confp;   // NOOBJ, tconf = 0
        }

        // ---- 8) block reduce -> partial; last block reduces NBLK partials
        #pragma unroll
        for (int o = 16; o > 0; o >>= 1)
            lcl += __shfl_xor_sync(FULL, lcl, o);
        if (lane == 0) swarp[tid >> 5] = lcl;
    }
    __syncthreads();
    if (tid < TPB / 32) {              // 16 lanes
        float v = swarp[tid];
        #pragma unroll
        for (int o = 8; o > 0; o >>= 1)
            v += __shfl_xor_sync(0xffffu, v, o);
        if (tid == 0) {
            g_partials[bid] = v;
            __threadfence();
            unsigned old = atomicAdd(&g_count, 1);
            s_last = (old == NBLK - 1) ? 1 : 0;
        }
    }
    __syncthreads();
    if (s_last) {
        if (tid < NBLK) {              // 128 lanes -> 4 warp sums
            float v = g_partials[tid];
            #pragma unroll
            for (int o = 16; o > 0; o >>= 1)
                v += __shfl_xor_sync(FULL, v, o);
            if ((tid & 31) == 0) swarp[tid >> 5] = v;
        }
        __syncthreads();
        if (tid == 0) {
            loss[0] = swarp[0] + swarp[1] + swarp[2] + swarp[3];
            g_count = 0;   // reset for next graph replay
        }
    }
}

extern "C" void kernel_launch(void* const* d_in, const int* in_sizes, int n_in,
                              void* d_out, int out_size)
{
    const float* output = (const float*)d_in[0];
    const float* target = (const float*)d_in[1];
    const int*   epoch  = (n_in > 2) ? (const int*)d_in[2] : nullptr;
    float* loss = (float*)d_out;

    region_loss_kernel<<<NBLK, TPB>>>(output, target, epoch, loss);
    (void)in_sizes; (void)out_size;
}

// round 10
// speedup vs baseline: 1.1830x; 1.1504x over previous
#include <cuda_runtime.h>

namespace {
constexpr int K     = 9;
constexpr int NB    = 64;
constexpr int NH    = 32;
constexpr int NW    = 32;
constexpr int NCELL = NH * NW;       // 1024
constexpr int NT    = 50;
constexpr int NLAB  = 2 * K + 3;     // 21
constexpr int CH    = 2 * K + 2;     // 20
constexpr float THR = 80.0f;
constexpr float IMW = 640.0f;
constexpr float IMH = 480.0f;
constexpr float SIL = 0.6f;
constexpr float OBJ = 5.0f;
constexpr int   TPB  = 1024;         // 2 threads per cell (paired lanes)
constexpr int   NBLK = 128;          // 128 CTAs, 1/SM, single wave
constexpr float CELLW = IMW / NW;    // 20 px
constexpr float CELLH = IMH / NH;    // 15 px
constexpr float THR2  = THR * THR;   // 6400
constexpr float GATE2 = 40.0f * 40.0f;  // silent needs >=5 corners within 40px
constexpr unsigned FULL = 0xffffffffu;
}

__device__ float        g_partials[NBLK];
__device__ unsigned int g_count = 0;

__global__ __launch_bounds__(TPB, 1) void region_loss_kernel(
    const float* __restrict__ out,
    const float* __restrict__ tgt,
    const int*   __restrict__ epoch_p,
    float*       __restrict__ loss)
{
    __shared__ float2 sXY[NT][K];                  // gt corners, pixel space
    __shared__ float swarp[TPB / 32];
    __shared__ int   s_last;

    const int bid  = blockIdx.x;
    const int b    = bid >> 1;
    const int tid  = threadIdx.x;
    const int lane = tid & 31;
    const int sub  = lane >> 4;                    // 0: corners 0-4, 1: corners 5-8
    const int wid  = tid >> 5;                     // warp covers 16 cells
    const int cell = ((bid & 1) << 9) | (wid << 4) | (lane & 15);
    const int wbase = cell & ~15;

    // ---- 1) loads first: 10 symmetric channels per thread
    const int epoch = epoch_p ? __ldg(epoch_p) : 20;
    const float* ob = out + (size_t)(b * CH) * NCELL + cell;
    float rx[5], ry[5];
    #pragma unroll
    for (int k = 0; k < 5; k++) {
        rx[k] = ob[(sub * 10 + 2 * k) * NCELL];
        ry[k] = ob[(sub * 10 + 2 * k + 1) * NCELL];
    }

    // ---- 2) stage targets (coalesced), pixel space — single barrier
    const float* tb = tgt + (size_t)b * (NT * NLAB);
    if (tid < NT * 2 * K) {
        int t = tid / (2 * K), c = tid - t * (2 * K);
        float v = tb[t * NLAB + 1 + c];
        float* dst = (float*)&sXY[t][c >> 1];
        dst[c & 1] = v * ((c & 1) ? IMH : IMW);
    }
    __syncthreads();

    // ---- 3) validity prefix + per-warp hit detection (lane-parallel, t<32)
    float2 c0l = sXY[lane][0];
    unsigned inv0 = ~__ballot_sync(FULL, c0l.x != 0.0f);
    bool v2 = (lane + 32 < NT) && (sXY[lane + 32][0].x != 0.0f);
    unsigned inv1 = ~__ballot_sync(FULL, v2);      // bits >= NT-32 always set
    const int nv = inv0 ? (__ffs(inv0) - 1) : (31 + __ffs(inv1));

    int gi0l = (int)floorf(c0l.x * (1.0f / CELLW));
    int gj0l = (int)floorf(c0l.y * (1.0f / CELLH));
    int cellv = (gi0l >= 0 && gi0l < NW && gj0l >= 0 && gj0l < NH)
                    ? gj0l * NW + gi0l : -1;
    cellv = (lane < nv) ? cellv : -1;
    unsigned hitm = __ballot_sync(FULL, (cellv >= wbase) && (cellv < wbase + 16));
    int thit = -1;
    for (unsigned hm = hitm; hm; hm &= hm - 1) {   // ascending t: last wins
        int t  = __ffs(hm) - 1;
        int sc = __shfl_sync(FULL, cellv, t);
        thit = (sc == cell) ? t : thit;
    }

    // ---- 4) predictions in pixel space (only global corner 0 is sigmoided)
    const bool do_conf = epoch > 15;
    const float i_f = (float)(cell & (NW - 1));
    const float j_f = (float)(cell >> 5);
    if (!sub) {
        rx[0] = 1.0f / (1.0f + __expf(-rx[0]));
        ry[0] = 1.0f / (1.0f + __expf(-ry[0]));
    }
    float confp = 1.0f / (1.0f + __expf(-__shfl_xor_sync(FULL, rx[4], 16)));

    float px[5], py[5];
    #pragma unroll
    for (int k = 0; k < 5; k++) {
        px[k] = (rx[k] + i_f) * CELLW;
        py[k] = (ry[k] + j_f) * CELLH;
    }

    const float inv_denK = (1.0f / (float)K) / (__expf(2.0f) - 1.0f + 1e-5f);

    // ---- 5) silent loop, targets t<32 (branchless cnt, rare exact exp path)
    bool silent = false;
    const int tmax = nv < 32 ? nv : 32;
    for (int t = 0; t < tmax; t++) {
        int cnt = 0;
        #pragma unroll
        for (int k = 0; k < 5; k++) {
            int kk = k + (sub ? 5 : 0); kk = kk > 8 ? 8 : kk;
            float2 g = sXY[t][kk];
            float dx = g.x - px[k], dy = g.y - py[k];
            float d2 = fmaf(dx, dx, dy * dy);
            if (k == 4) d2 = sub ? 3.0e38f : d2;   // mask dummy corner
            cnt += (d2 < GATE2);
        }
        cnt += __shfl_xor_sync(FULL, cnt, 16);     // pair combine (9 corners)
        bool hot = (cnt >= 5);                     // exact: silent => >=5 within 40px
        if (__any_sync(FULL, hot)) {               // warp-uniform branch
            float acc = 0.0f;
            #pragma unroll
            for (int k = 0; k < 5; k++) {
                int kk = k + (sub ? 5 : 0); kk = kk > 8 ? 8 : kk;
                float2 g = sXY[t][kk];
                float dx = g.x - px[k], dy = g.y - py[k];
                float d2 = fmaf(dx, dx, dy * dy);
                if (k == 4) d2 = sub ? 3.0e38f : d2;
                float cc = __expf(2.0f - sqrtf(d2) * (2.0f / THR)) - 1.0f;
                acc += (d2 < THR2) ? cc : 0.0f;
            }
            acc += __shfl_xor_sync(FULL, acc, 16);
            silent |= hot && (acc * inv_denK > SIL);
        }
    }

    // ---- 5b) rare general path for targets t in [32, nv)
    for (int t = 32; t < nv; t++) {
        float2 c0 = sXY[t][0];
        int gi = (int)floorf(c0.x * (1.0f / CELLW));
        int gj = (int)floorf(c0.y * (1.0f / CELLH));
        int sc = (gi >= 0 && gi < NW && gj >= 0 && gj < NH) ? gj * NW + gi : -1;
        thit = (sc == cell) ? t : thit;
        int cnt = 0;
        #pragma unroll
        for (int k = 0; k < 5; k++) {
            int kk = k + (sub ? 5 : 0); kk = kk > 8 ? 8 : kk;
            float2 g = sXY[t][kk];
            float dx = g.x - px[k], dy = g.y - py[k];
            float d2 = fmaf(dx, dx, dy * dy);
            if (k == 4) d2 = sub ? 3.0e38f : d2;
            cnt += (d2 < GATE2);
        }
        cnt += __shfl_xor_sync(FULL, cnt, 16);
        bool hot = (cnt >= 5);
        if (__any_sync(FULL, hot)) {
            float acc = 0.0f;
            #pragma unroll
            for (int k = 0; k < 5; k++) {
                int kk = k + (sub ? 5 : 0); kk = kk > 8 ? 8 : kk;
                float2 g = sXY[t][kk];
                float dx = g.x - px[k], dy = g.y - py[k];
                float d2 = fmaf(dx, dx, dy * dy);
                if (k == 4) d2 = sub ? 3.0e38f : d2;
                float cc = __expf(2.0f - sqrtf(d2) * (2.0f / THR)) - 1.0f;
                acc += (d2 < THR2) ? cc : 0.0f;
            }
            acc += __shfl_xor_sync(FULL, acc, 16);
            silent |= hot && (acc * inv_denK > SIL);
        }
    }

    // ---- 6) per-cell loss. Hit epilogue is WARP-UNIFORM: all lanes run the
    // body (index clamped), shuffles stay converged, results applied per-lane.
    float lcl = 0.0f;
    if (__any_sync(FULL, thit >= 0)) {
        const int th = (thit >= 0) ? thit : 0;
        float2 g0 = sXY[th][0];
        float gx0 = floorf(g0.x * (1.0f / CELLW));
        float gy0 = floorf(g0.y * (1.0f / CELLH));
        float closs = 0.0f, acc = 0.0f;
        #pragma unroll
        for (int k = 0; k < 5; k++) {
            int kk = k + (sub ? 5 : 0); kk = kk > 8 ? 8 : kk;
            float2 g = sXY[th][kk];
            float w  = (sub && k == 4) ? 0.0f : 1.0f;   // mask dummy
            float ex = rx[k] - (g.x * (1.0f / CELLW) - gx0);
            float ey = ry[k] - (g.y * (1.0f / CELLH) - gy0);
            closs += 0.5f * w * (ex * ex + ey * ey);
            float dx = g.x - px[k], dy = g.y - py[k];
            float d2 = fmaf(dx, dx, dy * dy);
            if (k == 4) d2 = sub ? 3.0e38f : d2;
            float cc = __expf(2.0f - sqrtf(d2) * (2.0f / THR)) - 1.0f;
            acc += (d2 < THR2) ? cc : 0.0f;
        }
        acc += __shfl_xor_sync(FULL, acc, 16);          // converged pair combine
        if (thit >= 0) {
            lcl += closs;
            if (do_conf && !sub) {
                float e = confp - acc * inv_denK;
                lcl += 0.5f * OBJ * e * e;
            }
        }
    }
    if (thit < 0 && do_conf && !sub)
        lcl += silent ? 0.0f : 0.5f * confp * confp;    // NOOBJ, tconf = 0

    // ---- 7) warp -> block -> grid reduction
    #pragma unroll
    for (int o = 16; o > 0; o >>= 1)
        lcl += __shfl_xor_sync(FULL, lcl, o);
    if (lane == 0) swarp[wid] = lcl;
    __syncthreads();
    if (tid < 32) {                   // 32 warps per CTA
        float v = swarp[tid];
        #pragma unroll
        for (int o = 16; o > 0; o >>= 1)
            v += __shfl_xor_sync(FULL, v, o);
        if (tid == 0) {
            g_partials[bid] = v;
            __threadfence();
            unsigned old = atomicAdd(&g_count, 1);
            s_last = (old == NBLK - 1) ? 1 : 0;
        }
    }
    __syncthreads();
    if (s_last) {
        if (tid < NBLK) {             // 128 partials -> 4 warp sums
            float v = g_partials[tid];
            #pragma unroll
            for (int o = 16; o > 0; o >>= 1)
                v += __shfl_xor_sync(FULL, v, o);
            if ((tid & 31) == 0) swarp[tid >> 5] = v;
        }
        __syncthreads();
        if (tid == 0) {
            loss[0] = swarp[0] + swarp[1] + swarp[2] + swarp[3];
            g_count = 0;              // reset for next graph replay
        }
    }
}

extern "C" void kernel_launch(void* const* d_in, const int* in_sizes, int n_in,
                              void* d_out, int out_size)
{
    const float* output = (const float*)d_in[0];
    const float* target = (const float*)d_in[1];
    const int*   epoch  = (n_in > 2) ? (const int*)d_in[2] : nullptr;
    float* loss = (float*)d_out;

    region_loss_kernel<<<NBLK, TPB>>>(output, target, epoch, loss);
    (void)in_sizes; (void)out_size;
}